// round 1
// baseline (speedup 1.0000x reference)
#include <cuda_runtime.h>

// DynamicLIF persistent kernel for GB300 (sm_103a).
// (B,T,C,H,W) = (32,8,128,32,32). mem state lives in registers across all T
// steps; per-batch software barriers (16 blocks/batch, all co-resident by
// construction) serialize the tiny tau-MLP between steps.

#define NB 32          // batch
#define NT 8           // time steps
#define NC 128         // channels
#define HW_ 1024       // H*W
#define CR 32          // C / red
#define THREADS 256
#define RPB 8          // channel rows per block
#define BPB 16         // blocks per batch (NC / RPB)
#define NBLOCKS (NB * BPB)   // 512

__device__ float    g_sums[NB * NC];
__device__ float    g_tau[NB];
__device__ unsigned g_count[NB];   // zero-init; returns to 0 each launch
__device__ unsigned g_gen[NB];     // monotonically increasing across replays

__global__ void __launch_bounds__(THREADS, 4)
lif_kernel(const float* __restrict__ x,
           const float* __restrict__ w1,
           const float* __restrict__ b1,
           const float* __restrict__ w2,
           const float* __restrict__ b2,
           float* __restrict__ out)
{
    __shared__ float s_w1[CR * NC];   // 16 KB, used by leader block only
    __shared__ float s_warp[8][RPB];
    __shared__ float s_mean[NC];
    __shared__ float s_tau;

    const int tid = threadIdx.x;
    const int blk = blockIdx.x;
    const int b   = blk >> 4;         // blk / BPB
    const int sub = blk & 15;         // blk % BPB
    const bool leader = (sub == 0);
    const int lane = tid & 31;
    const int warp = tid >> 5;

    // Leader block caches w1 in shared once for all steps.
    if (leader) {
        #pragma unroll
        for (int i = 0; i < (CR * NC) / THREADS; i++)
            s_w1[i * THREADS + tid] = w1[i * THREADS + tid];
    }
    __syncthreads();

    // Generation base: stable at launch (all prior barrier rounds complete),
    // makes the barrier correct across CUDA-graph replays.
    unsigned base_gen = 0;
    if (tid == 0) base_gen = *(volatile unsigned*)&g_gen[b];

    float tau = 0.5f;                 // TAU0
    float4 mem[RPB];
    #pragma unroll
    for (int i = 0; i < RPB; i++) mem[i] = make_float4(0.f, 0.f, 0.f, 0.f);

    // This block owns channels c in [sub*RPB, sub*RPB+RPB) of batch b, all HW.
    const size_t row_base = ((size_t)b * NT * NC + (size_t)sub * RPB) * HW_;

    for (int t = 0; t < NT; t++) {
        const float4* xp = (const float4*)(x   + row_base + (size_t)t * NC * HW_);
        float4*       op = (float4*)      (out + row_base + (size_t)t * NC * HW_);

        // ---- 1) mem = mem*tau + x  (separate mul+add to match JAX rounding),
        //         per-row partial sums for the mean ----
        float part[RPB];
        #pragma unroll
        for (int i = 0; i < RPB; i++) {
            float4 xv = __ldcs(xp + i * THREADS + tid);
            float4 m = mem[i];
            m.x = __fadd_rn(__fmul_rn(m.x, tau), xv.x);
            m.y = __fadd_rn(__fmul_rn(m.y, tau), xv.y);
            m.z = __fadd_rn(__fmul_rn(m.z, tau), xv.z);
            m.w = __fadd_rn(__fmul_rn(m.w, tau), xv.w);
            mem[i] = m;
            part[i] = (m.x + m.y) + (m.z + m.w);
        }

        const bool need_tau = (t < NT - 1);   // last step needs no tau/MLP

        if (need_tau) {
            // Row i of this block covers exactly 1024 contiguous floats:
            // warp-reduce, then 8 warp partials per row.
            #pragma unroll
            for (int i = 0; i < RPB; i++) {
                float v = part[i];
                v += __shfl_xor_sync(0xffffffffu, v, 16);
                v += __shfl_xor_sync(0xffffffffu, v, 8);
                v += __shfl_xor_sync(0xffffffffu, v, 4);
                v += __shfl_xor_sync(0xffffffffu, v, 2);
                v += __shfl_xor_sync(0xffffffffu, v, 1);
                if (lane == 0) s_warp[warp][i] = v;
            }
            __syncthreads();
            if (tid < RPB) {
                float s = 0.f;
                #pragma unroll
                for (int w = 0; w < 8; w++) s += s_warp[w][tid];
                __stcg(&g_sums[b * NC + sub * RPB + tid], s);
            }
            __threadfence();
            __syncthreads();
            if (tid == 0) atomicAdd(&g_count[b], 1u);
        }

        // ---- 2) spike + output + soft reset (overlaps barrier latency) ----
        #pragma unroll
        for (int i = 0; i < RPB; i++) {
            float4 m = mem[i];
            float4 sp;
            sp.x = (m.x > 1.0f) ? 1.0f : 0.0f;
            sp.y = (m.y > 1.0f) ? 1.0f : 0.0f;
            sp.z = (m.z > 1.0f) ? 1.0f : 0.0f;
            sp.w = (m.w > 1.0f) ? 1.0f : 0.0f;
            __stcs(op + i * THREADS + tid, sp);
            m.x = (m.x > 1.0f) ? 0.0f : m.x;
            m.y = (m.y > 1.0f) ? 0.0f : m.y;
            m.z = (m.z > 1.0f) ? 0.0f : m.z;
            m.w = (m.w > 1.0f) ? 0.0f : m.w;
            mem[i] = m;
        }

        if (!need_tau) break;

        // ---- 3) leader: wait for all 16 blocks' sums, run the MLP ----
        if (leader) {
            if (tid == 0) {
                while (*(volatile unsigned*)&g_count[b] != BPB) { }
                *(volatile unsigned*)&g_count[b] = 0;   // reset for next round
            }
            __syncthreads();
            __threadfence();
            if (tid < NC)
                s_mean[tid] = __ldcg(&g_sums[b * NC + tid]) * (1.0f / 1024.0f);
            __syncthreads();
            if (tid < CR) {
                float acc = b1[tid];
                #pragma unroll
                for (int c = 0; c < NC; c++)
                    acc = fmaf(s_w1[tid * NC + c], s_mean[c], acc);
                float e = fmaxf(acc, 0.0f);       // relu
                float p = e * w2[tid];
                p += __shfl_xor_sync(0xffffffffu, p, 16);
                p += __shfl_xor_sync(0xffffffffu, p, 8);
                p += __shfl_xor_sync(0xffffffffu, p, 4);
                p += __shfl_xor_sync(0xffffffffu, p, 2);
                p += __shfl_xor_sync(0xffffffffu, p, 1);
                if (tid == 0) {
                    float z = p + b2[0];
                    float tn = 1.0f / (1.0f + expf(-z));   // sigmoid
                    __stcg(&g_tau[b], tn);
                    __threadfence();                        // orders tau + count reset
                    atomicAdd(&g_gen[b], 1u);               // release
                }
            }
        }

        // ---- 4) all blocks: wait for new tau ----
        if (tid == 0) {
            unsigned tgt = base_gen + (unsigned)(t + 1);
            while (*(volatile unsigned*)&g_gen[b] != tgt) { }
            s_tau = __ldcg(&g_tau[b]);
        }
        __syncthreads();
        tau = s_tau;
    }
}

extern "C" void kernel_launch(void* const* d_in, const int* in_sizes, int n_in,
                              void* d_out, int out_size)
{
    const float* x  = (const float*)d_in[0];
    const float* w1 = (const float*)d_in[1];
    const float* b1 = (const float*)d_in[2];
    const float* w2 = (const float*)d_in[3];
    const float* b2 = (const float*)d_in[4];
    float* out = (float*)d_out;

    lif_kernel<<<NBLOCKS, THREADS>>>(x, w1, b1, w2, b2, out);
}